// round 3
// baseline (speedup 1.0000x reference)
#include <cuda_runtime.h>
#include <math.h>
#include <stdint.h>

#define NMB  4
#define CNUM 17
#define HNUM 8
#define BNUM 8
#define SLEN 512
#define DDIM 64
#define TI   64          // rows per block
#define JT   128         // j chunk per class pass
#define KSTR 68          // Ks row stride (floats): conflict-free, 16B-aligned rows
#define USTRD 68         // U row stride
#define MAXCH 12

// Premixed W1_^T: [C][h][n][m]  (transposed so a W column is contiguous)
__device__ float g_W[CNUM * HNUM * DDIM * DDIM];

// ---- packed f32x2 helpers ----
union F4U   { float4 f4; unsigned long long u[2]; };
union U64F2 { unsigned long long u; float2 f; };

__device__ __forceinline__ void ffma2(unsigned long long& d,
                                      unsigned long long a,
                                      unsigned long long b) {
    asm("fma.rn.f32x2 %0, %1, %2, %0;" : "+l"(d) : "l"(a), "l"(b));
}
__device__ __forceinline__ float hadd2(unsigned long long a) {
    U64F2 x; x.u = a; return x.f.x + x.f.y;
}

#define CP_COMMIT() asm volatile("cp.async.commit_group;")
#define CP_WAIT0()  asm volatile("cp.async.wait_group 0;" ::: "memory")

// ---------------- Kernel 1: W^T[c,h][n][m] = sum_B softmax(alpha1)[c,B,h] * W1[B,h][m][n]
__global__ void wmix_kernel(const float* __restrict__ W1,
                            const float* __restrict__ alpha1) {
    int c = blockIdx.x;   // 0..16
    int h = blockIdx.y;   // 0..7
    float a[NMB];
#pragma unroll
    for (int B = 0; B < NMB; B++) a[B] = alpha1[(c * NMB + B) * HNUM + h];
    float mx = fmaxf(fmaxf(a[0], a[1]), fmaxf(a[2], a[3]));
    float w[NMB], s = 0.f;
#pragma unroll
    for (int B = 0; B < NMB; B++) { w[B] = __expf(a[B] - mx); s += w[B]; }
    float inv = 1.f / s;
#pragma unroll
    for (int B = 0; B < NMB; B++) w[B] *= inv;

    float* dst = g_W + (c * HNUM + h) * DDIM * DDIM;
    const float* src = W1 + h * DDIM * DDIM;
    for (int e = threadIdx.x; e < DDIM * DDIM; e += blockDim.x) {
        int m = e >> 6, nn = e & 63;
        float v = 0.f;
#pragma unroll
        for (int B = 0; B < NMB; B++) v += w[B] * src[B * HNUM * DDIM * DDIM + e];
        dst[nn * DDIM + m] = v;   // transposed store
    }
}

// ---------------- Kernel 2 ----------------
// shared layout (bytes):
#define OFF_QS   0                            // 16384
#define OFF_U    16384                        // 64*68*4 = 17408
#define OFF_KS   (16384 + 17408)              // 2 buffers * 128*68*4 = 69632
#define OFF_INT  (OFF_KS + 2 * JT * KSTR * 4)
// ints: bj_all[512] jperm[512] jcnt[8] joff[8] jpos[8] rcnt[8] rlist[256]
//       cls[12] coff[12] clen[12] nch[4]
#define NINTS (512 + 512 + 8 + 8 + 8 + 8 + 256 + MAXCH * 3 + 4)
#define SMEM_BYTES (OFF_INT + NINTS * 4)

__global__ __launch_bounds__(256, 2)
void mb_scores_kernel(const float* __restrict__ q,
                      const float* __restrict__ k,
                      const int*   __restrict__ bseq,
                      float* __restrict__ out) {
    extern __shared__ unsigned char smraw[];
    float* Qs = (float*)(smraw + OFF_QS);
    float* Us = (float*)(smraw + OFF_U);
    float* Ks = (float*)(smraw + OFF_KS);     // 2 buffers of JT*KSTR
    int* bj_all = (int*)(smraw + OFF_INT);
    int* jperm  = bj_all + 512;
    int* jcnt   = jperm + 512;
    int* joff   = jcnt + 8;
    int* jpos   = joff + 8;
    int* rcnt   = jpos + 8;
    int* rlist  = rcnt + 8;
    int* cls    = rlist + 256;
    int* coff   = cls + MAXCH;
    int* clen   = coff + MAXCH;
    int* nchS   = clen + MAXCH;

    const int tid = threadIdx.x;
    const int it  = blockIdx.x;
    const int h   = blockIdx.y;
    const int b   = blockIdx.z;
    const int i0  = it * TI;

    const float* qbase = q + ((size_t)(b * HNUM + h) * SLEN + i0) * DDIM;
    const float* kbase = k + ((size_t)(b * HNUM + h) * SLEN) * DDIM;

    // load Q tile (64x64) as float4
    for (int t = tid; t < TI * DDIM / 4; t += 256)
        ((float4*)Qs)[t] = ((const float4*)qbase)[t];
    for (int t = tid; t < SLEN; t += 256) bj_all[t] = bseq[b * SLEN + t];
    if (tid < 8) { jcnt[tid] = 0; rcnt[tid] = 0; }
    __syncthreads();

    for (int t = tid; t < SLEN; t += 256) atomicAdd(&jcnt[bj_all[t]], 1);
    __syncthreads();
    if (tid == 0) {
        int s = 0;
        for (int t = 0; t < 5; t++) { joff[t] = s; jpos[t] = s; s += jcnt[t]; }
        int nc = 0;
        for (int t = 0; t < 5; t++) {
            int nt = jcnt[t], off = joff[t];
            for (int j0 = 0; j0 < nt; j0 += JT) {
                cls[nc] = t; coff[nc] = off + j0;
                clen[nc] = (nt - j0 < JT) ? (nt - j0) : JT;
                nc++;
            }
        }
        nchS[0] = nc;
    }
    __syncthreads();
    for (int t = tid; t < SLEN; t += 256) {
        int c = bj_all[t];
        int p = atomicAdd(&jpos[c], 1);
        jperm[p] = t;
    }
    for (int t = tid; t < TI; t += 256) {
        int c = bj_all[i0 + t];
        if (c > 0) { int p = atomicAdd(&rcnt[c - 1], 1); rlist[(c - 1) * 64 + p] = t; }
    }
    __syncthreads();

    const int ncls = nchS[0];
    const int n = tid & 63;
    const int g = tid >> 6;   // 0..3

    // ---- prologue: async-gather chunk 0 while computing Phase A0 ----
    {
        int len = clen[0], off = coff[0];
#pragma unroll
        for (int itr = 0; itr < 8; itr++) {
            int x = tid + itr * 256;
            int r = x >> 4, mb = x & 15;
            int rr = (r < len) ? r : (len - 1);
            const float* src = kbase + (size_t)jperm[off + rr] * DDIM + mb * 4;
            uint32_t daddr = (uint32_t)__cvta_generic_to_shared(Ks + r * KSTR + mb * 4);
            int sz = (r < len) ? 16 : 0;
            asm volatile("cp.async.ca.shared.global [%0], [%1], 16, %2;"
                         :: "r"(daddr), "l"(src), "r"(sz));
        }
        CP_COMMIT();
    }

    // ---- Phase A0: U[i][n] = sum_m Q[i][m] * W0[m][n], all 64 rows ----
    {
        const F4U* Wt = (const F4U*)(g_W + (size_t)h * DDIM * DDIM + n * DDIM); // c=0
        unsigned long long wp[32];
#pragma unroll
        for (int qd = 0; qd < 16; qd++) {
            F4U w4 = Wt[qd];
            wp[2 * qd] = w4.u[0]; wp[2 * qd + 1] = w4.u[1];
        }
#pragma unroll 1
        for (int r = 0; r < 16; r += 2) {
            int i = g * 16 + r;
            const F4U* qa = (const F4U*)(Qs + i * DDIM);
            const F4U* qb = (const F4U*)(Qs + (i + 1) * DDIM);
            unsigned long long a0 = 0, a1 = 0, b0 = 0, b1 = 0;
#pragma unroll
            for (int mb = 0; mb < 16; mb++) {
                F4U va = qa[mb], vb = qb[mb];
                ffma2(a0, va.u[0], wp[2 * mb]);
                ffma2(a1, va.u[1], wp[2 * mb + 1]);
                ffma2(b0, vb.u[0], wp[2 * mb]);
                ffma2(b1, vb.u[1], wp[2 * mb + 1]);
            }
            Us[i * USTRD + n]       = hadd2(a0) + hadd2(a1);
            Us[(i + 1) * USTRD + n] = hadd2(b0) + hadd2(b1);
        }
    }
    CP_WAIT0();
    __syncthreads();   // Ks buf0 + U(slot0 everywhere) ready

    const int tx = tid & 31, ty = tid >> 5;   // 32 x 8
    float* outbase = out + ((size_t)(b * HNUM + h) * SLEN + i0) * SLEN;

    int prevClass = 0;
    for (int c = 0; c < ncls; c++) {
        const int t = cls[c];
        float* Kbuf = Ks + (c & 1) * (JT * KSTR);

        // async prefetch of chunk c+1 into the other buffer
        if (c + 1 < ncls) {
            int len = clen[c + 1], off = coff[c + 1];
            float* dst = Ks + ((c + 1) & 1) * (JT * KSTR);
#pragma unroll
            for (int itr = 0; itr < 8; itr++) {
                int x = tid + itr * 256;
                int r = x >> 4, mb = x & 15;
                int rr = (r < len) ? r : (len - 1);
                const float* src = kbase + (size_t)jperm[off + rr] * DDIM + mb * 4;
                uint32_t daddr = (uint32_t)__cvta_generic_to_shared(dst + r * KSTR + mb * 4);
                int sz = (r < len) ? 16 : 0;
                asm volatile("cp.async.ca.shared.global [%0], [%1], 16, %2;"
                             :: "r"(daddr), "l"(src), "r"(sz));
            }
            CP_COMMIT();
        }

        // class transition: recompute U rows with bi>0 for class t
        if (t != prevClass && t > 0) {
            int v = g + 1;
            int cnt = rcnt[v - 1];
            if (cnt > 0) {
                int cc = 4 * (v - 1) + t;
                const F4U* Wt = (const F4U*)(g_W + (size_t)(cc * HNUM + h) * DDIM * DDIM + n * DDIM);
                unsigned long long wp[32];
#pragma unroll
                for (int qd = 0; qd < 16; qd++) {
                    F4U w4 = Wt[qd];
                    wp[2 * qd] = w4.u[0]; wp[2 * qd + 1] = w4.u[1];
                }
                int r = 0;
#pragma unroll 1
                for (; r + 1 < cnt; r += 2) {
                    int ia = rlist[(v - 1) * 64 + r];
                    int ib = rlist[(v - 1) * 64 + r + 1];
                    const F4U* qa = (const F4U*)(Qs + ia * DDIM);
                    const F4U* qb = (const F4U*)(Qs + ib * DDIM);
                    unsigned long long a0 = 0, a1 = 0, b0 = 0, b1 = 0;
#pragma unroll
                    for (int mb = 0; mb < 16; mb++) {
                        F4U va = qa[mb], vb = qb[mb];
                        ffma2(a0, va.u[0], wp[2 * mb]);
                        ffma2(a1, va.u[1], wp[2 * mb + 1]);
                        ffma2(b0, vb.u[0], wp[2 * mb]);
                        ffma2(b1, vb.u[1], wp[2 * mb + 1]);
                    }
                    Us[ia * USTRD + n] = hadd2(a0) + hadd2(a1);
                    Us[ib * USTRD + n] = hadd2(b0) + hadd2(b1);
                }
                if (r < cnt) {
                    int ia = rlist[(v - 1) * 64 + r];
                    const F4U* qa = (const F4U*)(Qs + ia * DDIM);
                    unsigned long long a0 = 0, a1 = 0;
#pragma unroll
                    for (int mb = 0; mb < 16; mb++) {
                        F4U va = qa[mb];
                        ffma2(a0, va.u[0], wp[2 * mb]);
                        ffma2(a1, va.u[1], wp[2 * mb + 1]);
                    }
                    Us[ia * USTRD + n] = hadd2(a0) + hadd2(a1);
                }
            }
            __syncthreads();   // U visible
        }

        // ---- compute chunk c: 8 rows x 4 cols packed acc per thread ----
        {
            unsigned long long acc[8][4];
#pragma unroll
            for (int ii = 0; ii < 8; ii++)
#pragma unroll
                for (int jj = 0; jj < 4; jj++) acc[ii][jj] = 0ull;

#pragma unroll
            for (int mb = 0; mb < 16; mb++) {
                F4U kv[4];
#pragma unroll
                for (int jj = 0; jj < 4; jj++)
                    kv[jj].f4 = *(const float4*)(Kbuf + (tx + jj * 32) * KSTR + mb * 4);
#pragma unroll
                for (int ii = 0; ii < 8; ii++) {
                    F4U av;
                    av.f4 = *(const float4*)(Us + (ty + ii * 8) * USTRD + mb * 4);
#pragma unroll
                    for (int jj = 0; jj < 4; jj++) {
                        ffma2(acc[ii][jj], av.u[0], kv[jj].u[0]);
                        ffma2(acc[ii][jj], av.u[1], kv[jj].u[1]);
                    }
                }
            }
            int chunk = clen[c], off = coff[c];
#pragma unroll
            for (int jj = 0; jj < 4; jj++) {
                int jc = tx + jj * 32;
                if (jc < chunk) {
                    int jp = jperm[off + jc];
#pragma unroll
                    for (int ii = 0; ii < 8; ii++)
                        outbase[(size_t)(ty + ii * 8) * SLEN + jp] = hadd2(acc[ii][jj]);
                }
            }
        }

        CP_WAIT0();
        __syncthreads();   // next buffer ready; compute done (safe to overwrite U / reuse buf)
        prevClass = t;
    }
}

// ---------------- launch ----------------
extern "C" void kernel_launch(void* const* d_in, const int* in_sizes, int n_in,
                              void* d_out, int out_size) {
    const float* q      = (const float*)d_in[0];
    const float* kk     = (const float*)d_in[1];
    const int*   bseq   = (const int*)  d_in[2];
    const float* W1     = (const float*)d_in[3];
    const float* alpha1 = (const float*)d_in[4];
    float* out = (float*)d_out;

    cudaFuncSetAttribute(mb_scores_kernel,
                         cudaFuncAttributeMaxDynamicSharedMemorySize, SMEM_BYTES);

    dim3 g1(CNUM, HNUM);
    wmix_kernel<<<g1, 256>>>(W1, alpha1);

    dim3 g2(SLEN / TI, HNUM, BNUM);   // 512 blocks
    mb_scores_kernel<<<g2, 256, SMEM_BYTES>>>(q, kk, bseq, out);
}